// round 3
// baseline (speedup 1.0000x reference)
#include <cuda_runtime.h>
#include <cstdint>

#define B 8
#define L 8192
#define C 512
#define NTOK (B * L)           // 65536
#define K_TOP 3687
#define K_RAND 409
#define NBINS 4096
#define SEL_THREADS 1024
#define SMEM_BYTES (32768 + 16384 + 32768 + 8192)   // scores + hist + cand + sel = 90112

// scratch (no allocations allowed)
__device__ float g_norms[NTOK];
__device__ unsigned char g_mask[NTOK];

// ---------------------------------------------------------------------------
// Kernel 1: token L2 norms. One warp per token (512 floats = 128 float4).
// ---------------------------------------------------------------------------
__global__ void norms_kernel(const float4* __restrict__ x) {
    int gw   = (blockIdx.x * blockDim.x + threadIdx.x) >> 5;   // token id
    int lane = threadIdx.x & 31;
    const float4* p = x + (size_t)gw * 128;
    float s = 0.f;
#pragma unroll
    for (int i = 0; i < 4; i++) {
        float4 v = p[lane + i * 32];
        s += v.x * v.x + v.y * v.y + v.z * v.z + v.w * v.w;
    }
#pragma unroll
    for (int o = 16; o; o >>= 1) s += __shfl_xor_sync(0xFFFFFFFFu, s, o);
    if (lane == 0) g_norms[gw] = sqrtf(s);
}

// ---------------------------------------------------------------------------
// threefry2x32, JAX-compatible. key = (0, 42) for jax.random.key(42).
// Partitionable scheme, bit_width=32 (jax/_src/prng.py,
// _threefry_random_bits_partitionable):
//   bits1, bits2 = threefry2x32(key, counts>>32, counts&0xffffffff)
//   return bits1 ^ bits2          <-- XOR of BOTH output words
// counts = iota(uint64, n), so hi=0, lo=i for our n=65536.
// ---------------------------------------------------------------------------
__device__ __forceinline__ uint32_t rotl32(uint32_t x, int d) {
    return (x << d) | (x >> (32 - d));
}

__device__ __forceinline__ uint32_t threefry_xor(uint32_t k1, uint32_t k2,
                                                 uint32_t x0, uint32_t x1) {
    uint32_t ks0 = k1, ks1 = k2, ks2 = k1 ^ k2 ^ 0x1BD11BDAu;
    x0 += ks0; x1 += ks1;
#define TF_R4(a,b,c,d) \
    x0 += x1; x1 = rotl32(x1, a); x1 ^= x0; \
    x0 += x1; x1 = rotl32(x1, b); x1 ^= x0; \
    x0 += x1; x1 = rotl32(x1, c); x1 ^= x0; \
    x0 += x1; x1 = rotl32(x1, d); x1 ^= x0;
    TF_R4(13, 15, 26, 6);  x0 += ks1; x1 += ks2 + 1u;
    TF_R4(17, 29, 16, 24); x0 += ks2; x1 += ks0 + 2u;
    TF_R4(13, 15, 26, 6);  x0 += ks0; x1 += ks1 + 3u;
    TF_R4(17, 29, 16, 24); x0 += ks1; x1 += ks2 + 4u;
    TF_R4(13, 15, 26, 6);  x0 += ks2; x1 += ks0 + 5u;
#undef TF_R4
    return x0 ^ x1;
}

// order-preserving float->uint map (handles negatives, e.g. the -1.0 sentinel)
__device__ __forceinline__ unsigned omap(float v) {
    unsigned u = __float_as_uint(v);
    return (u & 0x80000000u) ? ~u : (u | 0x80000000u);
}

// ---------------------------------------------------------------------------
// Exact k-th-largest 64-bit key over 8192 scores within one block.
// key(l) = (omap(score[l]) << 32) | (0xFFFFFFFF - l)  -> all keys distinct,
// tie-break = smaller index wins (matches jax.lax.top_k).
// Histogram in order-mapped uint space (integer math -> strictly monotone),
// suffix scan, gather boundary bin, O(cnt^2) rank select.
// ---------------------------------------------------------------------------
__device__ unsigned long long block_select(const float* sc, unsigned* hist,
                                           unsigned long long* cand, int k, int tid) {
    __shared__ unsigned s_umin, s_umax;
    __shared__ int s_bin, s_need, s_cnt;
    __shared__ unsigned long long s_thr;
    if (tid == 0) { s_umin = 0xFFFFFFFFu; s_umax = 0u; s_cnt = 0; }

    unsigned um[8];
    unsigned lmin = 0xFFFFFFFFu, lmax = 0u;
#pragma unroll
    for (int j = 0; j < 8; j++) {
        int l = tid + j * SEL_THREADS;
        unsigned u = omap(sc[l]);
        um[j] = u;
        lmin = min(lmin, u);
        lmax = max(lmax, u);
    }
#pragma unroll
    for (int j = 0; j < 4; j++) hist[tid + j * SEL_THREADS] = 0u;
    __syncthreads();               // s_umin/s_umax init + hist zero visible
    atomicMin(&s_umin, lmin);
    atomicMax(&s_umax, lmax);
    __syncthreads();

    unsigned umin = s_umin;
    unsigned long long span = (unsigned long long)(s_umax - umin) + 1ull;
#pragma unroll
    for (int j = 0; j < 8; j++) {
        unsigned b = (unsigned)(((unsigned long long)(um[j] - umin) * (unsigned long long)NBINS) / span);
        atomicAdd(&hist[b], 1u);
    }
    __syncthreads();

    // inclusive suffix sum: hist[i] = count of elements in bins [i, NBINS)
    for (int off = 1; off < NBINS; off <<= 1) {
        unsigned v[4];
#pragma unroll
        for (int j = 0; j < 4; j++) {
            int idx = tid + j * SEL_THREADS;
            unsigned val = hist[idx];
            if (idx + off < NBINS) val += hist[idx + off];
            v[j] = val;
        }
        __syncthreads();
#pragma unroll
        for (int j = 0; j < 4; j++) hist[tid + j * SEL_THREADS] = v[j];
        __syncthreads();
    }

    // boundary bin: geq(b) >= k and above(b) < k (unique since suffix monotone)
#pragma unroll
    for (int j = 0; j < 4; j++) {
        int idx = tid + j * SEL_THREADS;
        int geq = (int)hist[idx];
        int abv = (idx < NBINS - 1) ? (int)hist[idx + 1] : 0;
        if (geq >= k && abv < k) { s_bin = idx; s_need = k - abv; }
    }
    __syncthreads();

    int bsel = s_bin;
#pragma unroll
    for (int j = 0; j < 8; j++) {
        int l = tid + j * SEL_THREADS;
        unsigned b = (unsigned)(((unsigned long long)(um[j] - umin) * (unsigned long long)NBINS) / span);
        if ((int)b == bsel) {
            int p = atomicAdd(&s_cnt, 1);
            if (p < NBINS)
                cand[p] = ((unsigned long long)um[j] << 32) | (unsigned)(0xFFFFFFFFu - (unsigned)l);
        }
    }
    __syncthreads();

    int cnt  = min(s_cnt, NBINS);
    int need = s_need;
    for (int i = tid; i < cnt; i += SEL_THREADS) {
        unsigned long long ki = cand[i];
        int r = 0;
        for (int j = 0; j < cnt; j++) r += (cand[j] > ki);
        if (r == need - 1) s_thr = ki;
    }
    __syncthreads();
    return s_thr;
}

// ---------------------------------------------------------------------------
// Kernel 2: per-row selection. Block = one batch row.
// Phase 1: top-K_TOP by norm. Phase 2: top-K_RAND by threefry uniform among
// the remaining positions (score = -1 at top positions, like the reference).
// ---------------------------------------------------------------------------
__global__ void select_kernel() {
    extern __shared__ unsigned char smraw[];
    float*              s_score = (float*)smraw;                          // 32768 B
    unsigned*           s_hist  = (unsigned*)(smraw + 32768);             // 16384 B
    unsigned long long* s_cand  = (unsigned long long*)(smraw + 49152);   // 32768 B
    unsigned char*      s_sel   = (unsigned char*)(smraw + 81920);        //  8192 B

    int row = blockIdx.x;
    int tid = threadIdx.x;
    const float* norms = &g_norms[row * L];

#pragma unroll
    for (int j = 0; j < 8; j++) {
        int l = tid + j * SEL_THREADS;
        s_score[l] = norms[l];
    }
    __syncthreads();

    unsigned long long thr = block_select(s_score, s_hist, s_cand, K_TOP, tid);
#pragma unroll
    for (int j = 0; j < 8; j++) {
        int l = tid + j * SEL_THREADS;
        unsigned long long key =
            ((unsigned long long)omap(s_score[l]) << 32) | (unsigned)(0xFFFFFFFFu - (unsigned)l);
        s_sel[l] = (key >= thr) ? 1 : 0;
    }
    __syncthreads();

    // jax.random.uniform(key(42), (B,L)) — partitionable threefry, 32-bit:
    // bits[i] = word0 ^ word1 of threefry2x32((0,42), hi=0, lo=i)
#pragma unroll
    for (int j = 0; j < 8; j++) {
        int l = tid + j * SEL_THREADS;
        unsigned i = (unsigned)(row * L + l);
        unsigned bits = threefry_xor(0u, 42u, 0u, i);
        float r = __uint_as_float((bits >> 9) | 0x3F800000u) - 1.0f;
        s_score[l] = s_sel[l] ? -1.0f : r;
    }
    __syncthreads();

    thr = block_select(s_score, s_hist, s_cand, K_RAND, tid);
#pragma unroll
    for (int j = 0; j < 8; j++) {
        int l = tid + j * SEL_THREADS;
        unsigned long long key =
            ((unsigned long long)omap(s_score[l]) << 32) | (unsigned)(0xFFFFFFFFu - (unsigned)l);
        g_mask[row * L + l] = s_sel[l] | ((key >= thr) ? 1 : 0);
    }
}

// ---------------------------------------------------------------------------
// Kernel 3: out = mask ? x : 0 (float4 per thread; reads x only where kept)
// ---------------------------------------------------------------------------
__global__ void scatter_kernel(const float4* __restrict__ x, float4* __restrict__ out) {
    int i = blockIdx.x * blockDim.x + threadIdx.x;   // 0 .. NTOK*128-1
    int token = i >> 7;                              // 128 float4 per token
    float4 v = make_float4(0.f, 0.f, 0.f, 0.f);
    if (g_mask[token]) v = x[i];
    out[i] = v;
}

extern "C" void kernel_launch(void* const* d_in, const int* in_sizes, int n_in,
                              void* d_out, int out_size) {
    (void)in_sizes; (void)n_in; (void)out_size;
    const float4* x  = (const float4*)d_in[0];
    float4*       out = (float4*)d_out;

    cudaFuncSetAttribute(select_kernel,
                         cudaFuncAttributeMaxDynamicSharedMemorySize, SMEM_BYTES);

    norms_kernel<<<NTOK * 32 / 256, 256>>>(x);
    select_kernel<<<B, SEL_THREADS, SMEM_BYTES>>>();
    scatter_kernel<<<NTOK * 128 / 256, 256>>>(x, out);
}

// round 4
// speedup vs baseline: 1.1880x; 1.1880x over previous
#include <cuda_runtime.h>
#include <cstdint>

#define B 8
#define L 8192
#define C 512
#define NTOK (B * L)           // 65536
#define K_TOP 3687
#define K_RAND 409
#define NBINS 4096
#define SEL_THREADS 1024
#define SMEM_BYTES (32768 + 16384 + 32768 + 8192)   // scores + hist + cand + sel = 90112

// scratch (no allocations allowed)
__device__ float g_norms[NTOK];
__device__ unsigned char g_mask[NTOK];

// ---------------------------------------------------------------------------
// Kernel 1: token L2 norms. 16 threads per token, 8 independent float4 loads
// per thread (MLP=8) to hide DRAM latency.
// ---------------------------------------------------------------------------
__global__ void norms_kernel(const float4* __restrict__ x) {
    int gt    = blockIdx.x * blockDim.x + threadIdx.x;
    int token = gt >> 4;
    int sub   = gt & 15;
    const float4* p = x + (size_t)token * 128;
    float s = 0.f;
#pragma unroll
    for (int i = 0; i < 8; i++) {
        float4 v = p[sub + i * 16];
        s += v.x * v.x + v.y * v.y + v.z * v.z + v.w * v.w;
    }
#pragma unroll
    for (int o = 8; o; o >>= 1) s += __shfl_xor_sync(0xFFFFFFFFu, s, o, 16);
    if (sub == 0) g_norms[token] = sqrtf(s);
}

// ---------------------------------------------------------------------------
// threefry2x32, JAX-compatible (partitionable, bit_width=32):
// bits[i] = word0 ^ word1 of threefry2x32(key=(0,42), hi=0, lo=i)
// ---------------------------------------------------------------------------
__device__ __forceinline__ uint32_t rotl32(uint32_t x, int d) {
    return (x << d) | (x >> (32 - d));
}

__device__ __forceinline__ uint32_t threefry_xor(uint32_t k1, uint32_t k2,
                                                 uint32_t x0, uint32_t x1) {
    uint32_t ks0 = k1, ks1 = k2, ks2 = k1 ^ k2 ^ 0x1BD11BDAu;
    x0 += ks0; x1 += ks1;
#define TF_R4(a,b,c,d) \
    x0 += x1; x1 = rotl32(x1, a); x1 ^= x0; \
    x0 += x1; x1 = rotl32(x1, b); x1 ^= x0; \
    x0 += x1; x1 = rotl32(x1, c); x1 ^= x0; \
    x0 += x1; x1 = rotl32(x1, d); x1 ^= x0;
    TF_R4(13, 15, 26, 6);  x0 += ks1; x1 += ks2 + 1u;
    TF_R4(17, 29, 16, 24); x0 += ks2; x1 += ks0 + 2u;
    TF_R4(13, 15, 26, 6);  x0 += ks0; x1 += ks1 + 3u;
    TF_R4(17, 29, 16, 24); x0 += ks1; x1 += ks2 + 4u;
    TF_R4(13, 15, 26, 6);  x0 += ks2; x1 += ks0 + 5u;
#undef TF_R4
    return x0 ^ x1;
}

// order-preserving float->uint map
__device__ __forceinline__ unsigned omap(float v) {
    unsigned u = __float_as_uint(v);
    return (u & 0x80000000u) ? ~u : (u | 0x80000000u);
}

// ---------------------------------------------------------------------------
// Exact k-th-largest 64-bit key over 8192 scores within one block.
// key(l) = (omap(score[l]) << 32) | (0xFFFFFFFF - l)  -> distinct keys,
// tie-break = smaller index wins (matches jax.lax.top_k).
// Low-barrier version: each thread owns 4 contiguous bins; suffix counts via
// in-register suffix + warp shfl suffix scan + 1-warp scan of warp sums.
// ---------------------------------------------------------------------------
__device__ unsigned long long block_select(const float* sc, unsigned* hist,
                                           unsigned long long* cand, int k, int tid) {
    __shared__ unsigned s_umin, s_umax;
    __shared__ int s_bin, s_need, s_cnt;
    __shared__ unsigned long long s_thr;
    __shared__ unsigned s_wsum[32];
    int lane = tid & 31, wid = tid >> 5;
    if (tid == 0) { s_umin = 0xFFFFFFFFu; s_umax = 0u; s_cnt = 0; }

    unsigned um[8];
    unsigned lmin = 0xFFFFFFFFu, lmax = 0u;
#pragma unroll
    for (int j = 0; j < 8; j++) {
        int l = tid + j * SEL_THREADS;
        unsigned u = omap(sc[l]);
        um[j] = u;
        lmin = min(lmin, u);
        lmax = max(lmax, u);
    }
    reinterpret_cast<uint4*>(hist)[tid] = make_uint4(0u, 0u, 0u, 0u);  // bins 4t..4t+3
    __syncthreads();
    atomicMin(&s_umin, lmin);
    atomicMax(&s_umax, lmax);
    __syncthreads();

    unsigned umin = s_umin;
    unsigned long long span = (unsigned long long)(s_umax - umin) + 1ull;
#pragma unroll
    for (int j = 0; j < 8; j++) {
        unsigned b = (unsigned)(((unsigned long long)(um[j] - umin) * (unsigned long long)NBINS) / span);
        atomicAdd(&hist[b], 1u);
    }
    __syncthreads();

    // suffix counts over the 4 bins this thread owns
    uint4 c = reinterpret_cast<const uint4*>(hist)[tid];
    unsigned s3 = c.w;
    unsigned s2 = c.z + s3;
    unsigned s1 = c.y + s2;
    unsigned s0 = c.x + s1;
    unsigned tot = s0;

    // warp inclusive suffix scan of thread totals (lane i -> sum of lanes i..31)
    unsigned inc = tot;
#pragma unroll
    for (int off = 1; off < 32; off <<= 1) {
        unsigned v = __shfl_down_sync(0xFFFFFFFFu, inc, off);
        if (lane < 32 - off) inc += v;
    }
    if (lane == 0) s_wsum[wid] = inc;
    __syncthreads();
    if (wid == 0) {
        unsigned v = s_wsum[lane];
        unsigned inc2 = v;
#pragma unroll
        for (int off = 1; off < 32; off <<= 1) {
            unsigned t = __shfl_down_sync(0xFFFFFFFFu, inc2, off);
            if (lane < 32 - off) inc2 += t;
        }
        s_wsum[lane] = inc2 - v;   // exclusive: count in warps > lane
    }
    __syncthreads();

    // count of elements in bins strictly above this thread's 4 bins
    unsigned above = s_wsum[wid] + (inc - tot);

    // boundary bin (suffix monotone non-increasing -> exactly one hit)
    {
        unsigned geq0 = above + s0, abv0 = above + s1;
        unsigned geq1 = above + s1, abv1 = above + s2;
        unsigned geq2 = above + s2, abv2 = above + s3;
        unsigned geq3 = above + s3, abv3 = above;
        unsigned uk = (unsigned)k;
        if (geq0 >= uk && abv0 < uk) { s_bin = 4 * tid + 0; s_need = k - (int)abv0; }
        if (geq1 >= uk && abv1 < uk) { s_bin = 4 * tid + 1; s_need = k - (int)abv1; }
        if (geq2 >= uk && abv2 < uk) { s_bin = 4 * tid + 2; s_need = k - (int)abv2; }
        if (geq3 >= uk && abv3 < uk) { s_bin = 4 * tid + 3; s_need = k - (int)abv3; }
    }
    __syncthreads();

    int bsel = s_bin;
#pragma unroll
    for (int j = 0; j < 8; j++) {
        int l = tid + j * SEL_THREADS;
        unsigned b = (unsigned)(((unsigned long long)(um[j] - umin) * (unsigned long long)NBINS) / span);
        if ((int)b == bsel) {
            int p = atomicAdd(&s_cnt, 1);
            if (p < NBINS)
                cand[p] = ((unsigned long long)um[j] << 32) | (unsigned)(0xFFFFFFFFu - (unsigned)l);
        }
    }
    __syncthreads();

    int cnt  = min(s_cnt, NBINS);
    int need = s_need;
    for (int i = tid; i < cnt; i += SEL_THREADS) {
        unsigned long long ki = cand[i];
        int r = 0;
        for (int j = 0; j < cnt; j++) r += (cand[j] > ki);
        if (r == need - 1) s_thr = ki;
    }
    __syncthreads();
    return s_thr;
}

// ---------------------------------------------------------------------------
// Kernel 2: per-row selection (block = batch row).
// ---------------------------------------------------------------------------
__global__ void select_kernel() {
    extern __shared__ unsigned char smraw[];
    float*              s_score = (float*)smraw;                          // 32768 B
    unsigned*           s_hist  = (unsigned*)(smraw + 32768);             // 16384 B
    unsigned long long* s_cand  = (unsigned long long*)(smraw + 49152);   // 32768 B
    unsigned char*      s_sel   = (unsigned char*)(smraw + 81920);        //  8192 B

    int row = blockIdx.x;
    int tid = threadIdx.x;
    const float* norms = &g_norms[row * L];

#pragma unroll
    for (int j = 0; j < 8; j++) {
        int l = tid + j * SEL_THREADS;
        s_score[l] = norms[l];
    }
    __syncthreads();

    unsigned long long thr = block_select(s_score, s_hist, s_cand, K_TOP, tid);
#pragma unroll
    for (int j = 0; j < 8; j++) {
        int l = tid + j * SEL_THREADS;
        unsigned long long key =
            ((unsigned long long)omap(s_score[l]) << 32) | (unsigned)(0xFFFFFFFFu - (unsigned)l);
        s_sel[l] = (key >= thr) ? 1 : 0;
    }
    __syncthreads();

#pragma unroll
    for (int j = 0; j < 8; j++) {
        int l = tid + j * SEL_THREADS;
        unsigned i = (unsigned)(row * L + l);
        unsigned bits = threefry_xor(0u, 42u, 0u, i);
        float r = __uint_as_float((bits >> 9) | 0x3F800000u) - 1.0f;
        s_score[l] = s_sel[l] ? -1.0f : r;
    }
    __syncthreads();

    thr = block_select(s_score, s_hist, s_cand, K_RAND, tid);
#pragma unroll
    for (int j = 0; j < 8; j++) {
        int l = tid + j * SEL_THREADS;
        unsigned long long key =
            ((unsigned long long)omap(s_score[l]) << 32) | (unsigned)(0xFFFFFFFFu - (unsigned)l);
        g_mask[row * L + l] = s_sel[l] | ((key >= thr) ? 1 : 0);
    }
}

// ---------------------------------------------------------------------------
// Kernel 3: out = mask ? x : 0.
// Reversed block order so the tail of x (most recently resident in L2 from
// norms_kernel's forward stream) is read first. Output stored with __stcs
// (evict-first) so the 128MB write stream doesn't evict x from L2.
// 2 float4 per thread (MLP 2). Block covers 4 tokens (512 float4).
// ---------------------------------------------------------------------------
__global__ void scatter_kernel(const float4* __restrict__ x, float4* __restrict__ out) {
    int rb   = gridDim.x - 1 - blockIdx.x;
    int base = rb * 512;
    int j    = threadIdx.x;
    int i0 = base + j;
    int i1 = base + 256 + j;
    unsigned m0 = g_mask[i0 >> 7];
    unsigned m1 = g_mask[i1 >> 7];
    float4 z = make_float4(0.f, 0.f, 0.f, 0.f);
    float4 v0 = m0 ? __ldg(&x[i0]) : z;
    float4 v1 = m1 ? __ldg(&x[i1]) : z;
    __stcs(&out[i0], v0);
    __stcs(&out[i1], v1);
}

extern "C" void kernel_launch(void* const* d_in, const int* in_sizes, int n_in,
                              void* d_out, int out_size) {
    (void)in_sizes; (void)n_in; (void)out_size;
    const float4* x   = (const float4*)d_in[0];
    float4*       out = (float4*)d_out;

    cudaFuncSetAttribute(select_kernel,
                         cudaFuncAttributeMaxDynamicSharedMemorySize, SMEM_BYTES);

    norms_kernel<<<NTOK * 16 / 256, 256>>>(x);
    select_kernel<<<B, SEL_THREADS, SMEM_BYTES>>>();
    scatter_kernel<<<NTOK * 128 / 512, 256>>>(x, out);
}